// round 4
// baseline (speedup 1.0000x reference)
#include <cuda_runtime.h>
#include <cuda_bf16.h>
#include <mma.h>

using namespace nvcuda;

#define N_NODES 100000
#define N_EDGES 1600000
#define DIM 128
#define ODIM 16
#define MLP_CTAS 782            // ceil(100000/128)
#define SP_CTAS  12500          // 8 nodes per CTA
#define ROLE_MOD 17             // bid % 17 == 0 -> MLP role
#define F_GRID   (MLP_CTAS * ROLE_MOD)   // 13294

// ---------------- static scratch (no allocs allowed) ----------------
__device__ float g_y1[N_NODES * DIM];
__device__ float g_y2[N_NODES * DIM];
__device__ int   g_deg[N_NODES];
__device__ int   g_start[N_NODES];
__device__ int   g_pos[N_NODES];
__device__ float g_dinv[N_NODES];
__device__ int   g_csr[N_EDGES];
__device__ int   g_cursor;
__device__ int   g_shift;   // 0 = int32 edge words, 1 = int64 (read low word)

// ---------------- dtype detect + zero ----------------
__global__ void k_zero(const int* __restrict__ eraw) {
    int i = blockIdx.x * blockDim.x + threadIdx.x;
    if (i < N_NODES) g_deg[i] = 0;
    if (i == 0) {
        g_cursor = 0;
        int is64 = 1;
        for (int e = 0; e < 64; e++) {
            if (eraw[2 * e + 1] != 0) { is64 = 0; break; }
        }
        g_shift = is64;
    }
}

__device__ __forceinline__ int edge_at(const int* __restrict__ eraw, long long pos) {
    return eraw[pos << g_shift];
}

// ---------------- CSR build ----------------
__global__ void k_count(const int* __restrict__ eraw) {
    int e = blockIdx.x * blockDim.x + threadIdx.x;
    if (e < N_EDGES) atomicAdd(&g_deg[edge_at(eraw, e)], 1);
}

__global__ void k_alloc() {
    int i = blockIdx.x * blockDim.x + threadIdx.x;
    if (i < N_NODES) {
        int d = g_deg[i];
        int s = atomicAdd(&g_cursor, d);
        g_start[i] = s;
        g_pos[i]   = s;
        g_dinv[i]  = 1.0f / (float)max(d, 1);
    }
}

__global__ void k_scatter(const int* __restrict__ eraw) {
    int e = blockIdx.x * blockDim.x + threadIdx.x;
    if (e < N_EDGES) {
        int r = edge_at(eraw, e);
        int c = edge_at(eraw, (long long)N_EDGES + e);
        int p = atomicAdd(&g_pos[r], 1);
        g_csr[p] = c;
    }
}

// ---------------- SpMM per-node (one warp), index-prefetch pipelined -------
__device__ __forceinline__ void spmm_node(int node, const float4* __restrict__ vin,
                                          float4* __restrict__ vout, int lane) {
    if (node >= N_NODES) return;
    int s = g_start[node];
    int d = g_deg[node];
    float4 acc = make_float4(0.f, 0.f, 0.f, 0.f);
    int c = (d > 0) ? __ldg(&g_csr[s]) : 0;
    #pragma unroll 2
    for (int k = 0; k < d; k++) {
        int cn = (k + 1 < d) ? __ldg(&g_csr[s + k + 1]) : 0;
        float4 v = __ldg(&vin[c * 32 + lane]);
        acc.x += v.x; acc.y += v.y; acc.z += v.z; acc.w += v.w;
        c = cn;
    }
    vout[node * 32 + lane] = acc;
}

// ---------------- MLP tile (one branch): tf32 WMMA stage1 + classifier ----
// smem S [128][132]: A tile during K loop, reused as Ht[n][m] for stage2.
#define LDS_T 132
#define SM_S     0                              // 128*132*4 = 67584
#define SM_WCS   67584                          // 2048*4    = 8192
#define SM_BIAS  75776                          // 128*4
#define SM_DSC   76288                          // 128*4
#define SM_TOTAL 76800

template <int SCALE_MODE, bool FIRST>
__device__ __forceinline__ void mlp_tile(
    int m0, const float* __restrict__ A, const float* __restrict__ W,
    const float* __restrict__ bias, const float* __restrict__ Wc_br,
    const float* __restrict__ bc, float* __restrict__ out, char* smem_raw) {

    float* S      = (float*)(smem_raw + SM_S);
    float* Wcs    = (float*)(smem_raw + SM_WCS);
    float* bias_s = (float*)(smem_raw + SM_BIAS);
    float* dsc    = (float*)(smem_raw + SM_DSC);

    const int tid = threadIdx.x;
    const int wid = tid >> 5;
    const int mrow0 = (wid & 3) * 32;
    const int ncol0 = (wid >> 2) * 64;
    const int oc = tid & 15;
    const int nb = (tid >> 4) * 8;

    // constants
    #pragma unroll
    for (int p = 0; p < 2; p++) {
        int t = tid + 256 * p;
        ((float4*)Wcs)[t] = __ldg(&((const float4*)Wc_br)[t]);
    }
    if (tid < 128) {
        bias_s[tid] = __ldg(&bias[tid]);
        if (SCALE_MODE == 0) dsc[tid] = 1.f;
        else {
            int m = m0 + tid;
            float di = (m < N_NODES) ? g_dinv[m] : 1.f;
            dsc[tid] = (SCALE_MODE == 1) ? di : di * di;
        }
    }

    // stage A tile into smem
    {
        int m    = tid >> 1;
        int half = (tid & 1) * 64;
        bool ok  = (m0 + m) < N_NODES;
        const float4* src = (const float4*)&A[(size_t)(m0 + m) * 128 + half];
        float4* dst = (float4*)&S[m * LDS_T + half];
        #pragma unroll
        for (int q = 0; q < 16; q++) {
            float4 v = ok ? __ldg(&src[q]) : make_float4(0.f, 0.f, 0.f, 0.f);
            dst[q] = v;
        }
    }
    __syncthreads();

    // K loop: tf32 WMMA, each warp 32x64
    wmma::fragment<wmma::accumulator, 16, 16, 8, float> acc[2][4];
    #pragma unroll
    for (int i = 0; i < 2; i++)
        #pragma unroll
        for (int j = 0; j < 4; j++) wmma::fill_fragment(acc[i][j], 0.f);

    #pragma unroll 4
    for (int k0 = 0; k0 < 128; k0 += 8) {
        wmma::fragment<wmma::matrix_a, 16, 16, 8, wmma::precision::tf32,
                       wmma::row_major> af[2];
        #pragma unroll
        for (int i = 0; i < 2; i++) {
            wmma::load_matrix_sync(af[i], S + (mrow0 + i * 16) * LDS_T + k0, LDS_T);
            #pragma unroll
            for (int e = 0; e < af[i].num_elements; e++)
                af[i].x[e] = wmma::__float_to_tf32(af[i].x[e]);
        }
        wmma::fragment<wmma::matrix_b, 16, 16, 8, wmma::precision::tf32,
                       wmma::row_major> bf[4];
        #pragma unroll
        for (int j = 0; j < 4; j++) {
            wmma::load_matrix_sync(bf[j], W + k0 * 128 + ncol0 + j * 16, 128);
            #pragma unroll
            for (int e = 0; e < bf[j].num_elements; e++)
                bf[j].x[e] = wmma::__float_to_tf32(bf[j].x[e]);
        }
        #pragma unroll
        for (int i = 0; i < 2; i++)
            #pragma unroll
            for (int j = 0; j < 4; j++)
                wmma::mma_sync(acc[i][j], af[i], bf[j], acc[i][j]);
    }
    __syncthreads();

    // store acc col-major into S as Ht[n][m]
    #pragma unroll
    for (int i = 0; i < 2; i++)
        #pragma unroll
        for (int j = 0; j < 4; j++)
            wmma::store_matrix_sync(S + (ncol0 + j * 16) * LDS_T + (mrow0 + i * 16),
                                    acc[i][j], LDS_T, wmma::mem_col_major);
    __syncthreads();

    // fixup: h = relu(acc * dsc[m] + bias[c]) in place
    {
        int c  = tid >> 1;
        int mh = (tid & 1) * 64;
        float bb = bias_s[c];
        #pragma unroll
        for (int q = 0; q < 16; q++) {
            int m = mh + q * 4;
            float4 v  = *(float4*)&S[c * LDS_T + m];
            float4 dv = *(const float4*)&dsc[m];
            v.x = fmaxf(fmaf(v.x, dv.x, bb), 0.f);
            v.y = fmaxf(fmaf(v.y, dv.y, bb), 0.f);
            v.z = fmaxf(fmaf(v.z, dv.z, bb), 0.f);
            v.w = fmaxf(fmaf(v.w, dv.w, bb), 0.f);
            *(float4*)&S[c * LDS_T + m] = v;
        }
    }
    __syncthreads();

    // stage2: out[nb..nb+8][oc] (+)= H @ Wc_br
    float oacc[8];
    #pragma unroll
    for (int i = 0; i < 8; i++) oacc[i] = 0.f;
    #pragma unroll 8
    for (int c = 0; c < 128; c++) {
        float w = Wcs[c * 16 + oc];
        float4 h0 = *(const float4*)&S[c * LDS_T + nb];
        float4 h1 = *(const float4*)&S[c * LDS_T + nb + 4];
        oacc[0] += h0.x * w; oacc[1] += h0.y * w;
        oacc[2] += h0.z * w; oacc[3] += h0.w * w;
        oacc[4] += h1.x * w; oacc[5] += h1.y * w;
        oacc[6] += h1.z * w; oacc[7] += h1.w * w;
    }

    if (FIRST) {
        float bcv = __ldg(&bc[oc]);
        #pragma unroll
        for (int i = 0; i < 8; i++) {
            int node = m0 + nb + i;
            if (node < N_NODES) out[node * 16 + oc] = oacc[i] + bcv;
        }
    } else {
        #pragma unroll
        for (int i = 0; i < 8; i++) {
            int node = m0 + nb + i;
            if (node < N_NODES) out[node * 16 + oc] += oacc[i];
        }
    }
}

// ---------------- fused kernels: MLP branch + SpMM, interleaved roles ------
__global__ __launch_bounds__(256, 2)
void k_f1(const float* __restrict__ x,
          const float* __restrict__ Wego, const float* __restrict__ bego,
          const float* __restrict__ Wc,   const float* __restrict__ bc,
          float* __restrict__ out, float4* __restrict__ y1) {
    extern __shared__ char smem_raw[];
    int bid = blockIdx.x;
    if (bid % ROLE_MOD == 0) {
        mlp_tile<0, true>((bid / ROLE_MOD) * 128, x, Wego, bego, Wc, bc, out, smem_raw);
    } else {
        int sid = bid - bid / ROLE_MOD - 1;
        if (sid < SP_CTAS)
            spmm_node(sid * 8 + (threadIdx.x >> 5), (const float4*)x, y1,
                      threadIdx.x & 31);
    }
}

__global__ __launch_bounds__(256, 2)
void k_f2(const float* __restrict__ y1f,
          const float* __restrict__ W1, const float* __restrict__ b1,
          const float* __restrict__ Wc,
          float* __restrict__ out, float4* __restrict__ y2) {
    extern __shared__ char smem_raw[];
    int bid = blockIdx.x;
    if (bid % ROLE_MOD == 0) {
        mlp_tile<1, false>((bid / ROLE_MOD) * 128, y1f, W1, b1, Wc + 2048,
                           nullptr, out, smem_raw);
    } else {
        int sid = bid - bid / ROLE_MOD - 1;
        if (sid < SP_CTAS)
            spmm_node(sid * 8 + (threadIdx.x >> 5), (const float4*)y1f, y2,
                      threadIdx.x & 31);
    }
}

__global__ __launch_bounds__(256, 2)
void k_f3(const float* __restrict__ y2f,
          const float* __restrict__ W2, const float* __restrict__ b2,
          const float* __restrict__ Wc, float* __restrict__ out) {
    extern __shared__ char smem_raw[];
    mlp_tile<2, false>(blockIdx.x * 128, y2f, W2, b2, Wc + 4096,
                       nullptr, out, smem_raw);
}

// ---------------- launch ----------------
extern "C" void kernel_launch(void* const* d_in, const int* in_sizes, int n_in,
                              void* d_out, int out_size) {
    const float* x    = (const float*)d_in[0];
    const int*   ei   = (const int*)d_in[1];
    const float* Wego = (const float*)d_in[2];
    const float* bego = (const float*)d_in[3];
    const float* W1   = (const float*)d_in[4];
    const float* b1   = (const float*)d_in[5];
    const float* W2   = (const float*)d_in[6];
    const float* b2   = (const float*)d_in[7];
    const float* Wc   = (const float*)d_in[8];
    const float* bc   = (const float*)d_in[9];
    float*       out  = (float*)d_out;

    void *py1 = nullptr, *py2 = nullptr;
    cudaGetSymbolAddress(&py1, g_y1);
    cudaGetSymbolAddress(&py2, g_y2);

    cudaFuncSetAttribute(k_f1, cudaFuncAttributeMaxDynamicSharedMemorySize, SM_TOTAL);
    cudaFuncSetAttribute(k_f2, cudaFuncAttributeMaxDynamicSharedMemorySize, SM_TOTAL);
    cudaFuncSetAttribute(k_f3, cudaFuncAttributeMaxDynamicSharedMemorySize, SM_TOTAL);

    k_zero<<<(N_NODES + 1023) / 1024, 1024>>>(ei);
    k_count<<<(N_EDGES + 255) / 256, 256>>>(ei);
    k_alloc<<<(N_NODES + 255) / 256, 256>>>();
    k_scatter<<<(N_EDGES + 255) / 256, 256>>>(ei);

    k_f1<<<F_GRID, 256, SM_TOTAL>>>(x, Wego, bego, Wc, bc, out, (float4*)py1);
    k_f2<<<F_GRID, 256, SM_TOTAL>>>((const float*)py1, W1, b1, Wc, out, (float4*)py2);
    k_f3<<<MLP_CTAS, 256, SM_TOTAL>>>((const float*)py2, W2, b2, Wc, out);
}

// round 5
// speedup vs baseline: 1.6834x; 1.6834x over previous
#include <cuda_runtime.h>
#include <cuda_bf16.h>
#include <mma.h>

using namespace nvcuda;

#define N_NODES 100000
#define N_EDGES 1600000
#define DIM 128
#define ODIM 16
#define MLP_CTAS 782            // ceil(100000/128)

// ---------------- static scratch (no allocs allowed) ----------------
__device__ float g_y1[N_NODES * DIM];
__device__ float g_y2[N_NODES * DIM];
__device__ int   g_deg[N_NODES];
__device__ int   g_start[N_NODES];
__device__ int   g_pos[N_NODES];
__device__ float g_dinv[N_NODES];
__device__ int   g_csr[N_EDGES];
__device__ int   g_cursor;
__device__ int   g_shift;   // 0 = int32 edge words, 1 = int64 (read low word)

// ---------------- dtype detect + zero ----------------
__global__ void k_zero(const int* __restrict__ eraw) {
    int i = blockIdx.x * blockDim.x + threadIdx.x;
    if (i < N_NODES) g_deg[i] = 0;
    if (i == 0) {
        g_cursor = 0;
        int is64 = 1;
        for (int e = 0; e < 64; e++) {
            if (eraw[2 * e + 1] != 0) { is64 = 0; break; }
        }
        g_shift = is64;
    }
}

__device__ __forceinline__ int edge_at(const int* __restrict__ eraw, long long pos) {
    return eraw[pos << g_shift];
}

// ---------------- CSR build ----------------
__global__ void k_count(const int* __restrict__ eraw) {
    int e = blockIdx.x * blockDim.x + threadIdx.x;
    if (e < N_EDGES) atomicAdd(&g_deg[edge_at(eraw, e)], 1);
}

__global__ void k_alloc() {
    int i = blockIdx.x * blockDim.x + threadIdx.x;
    if (i < N_NODES) {
        int d = g_deg[i];
        int s = atomicAdd(&g_cursor, d);
        g_start[i] = s;
        g_pos[i]   = s;
        g_dinv[i]  = 1.0f / (float)max(d, 1);
    }
}

__global__ void k_scatter(const int* __restrict__ eraw) {
    int e = blockIdx.x * blockDim.x + threadIdx.x;
    if (e < N_EDGES) {
        int r = edge_at(eraw, e);
        int c = edge_at(eraw, (long long)N_EDGES + e);
        int p = atomicAdd(&g_pos[r], 1);
        g_csr[p] = c;
    }
}

// ---------------- SpMM: y[i,:] = sum_{j in adj(i)} v[j,:] ----------------
__global__ void k_spmm(const float4* __restrict__ vin, float4* __restrict__ vout) {
    int node = blockIdx.x * blockDim.y + threadIdx.y;
    if (node >= N_NODES) return;
    int lane = threadIdx.x;
    int s = g_start[node];
    int d = g_deg[node];
    float4 acc = make_float4(0.f, 0.f, 0.f, 0.f);
    int c = (d > 0) ? __ldg(&g_csr[s]) : 0;
    #pragma unroll 2
    for (int k = 0; k < d; k++) {
        int cn = (k + 1 < d) ? __ldg(&g_csr[s + k + 1]) : 0;
        float4 v = __ldg(&vin[c * 32 + lane]);
        acc.x += v.x; acc.y += v.y; acc.z += v.z; acc.w += v.w;
        c = cn;
    }
    vout[node * 32 + lane] = acc;
}

// ---------------- MLP tile (one branch): tf32 WMMA stage1 + classifier ----
// smem S [128][132]: A tile during K loop, reused as Ht[n][m] for stage2.
#define LDS_T 132
#define SM_S     0                              // 128*132*4 = 67584
#define SM_WCS   67584                          // 2048*4
#define SM_BIAS  75776                          // 128*4
#define SM_DSC   76288                          // 128*4
#define SM_TOTAL 76800

template <int SCALE_MODE, bool FIRST>
__device__ __forceinline__ void mlp_tile(
    int m0, const float* __restrict__ A, const float* __restrict__ W,
    const float* __restrict__ bias, const float* __restrict__ Wc_br,
    const float* __restrict__ bc, float* __restrict__ out, char* smem_raw) {

    float* S      = (float*)(smem_raw + SM_S);
    float* Wcs    = (float*)(smem_raw + SM_WCS);
    float* bias_s = (float*)(smem_raw + SM_BIAS);
    float* dsc    = (float*)(smem_raw + SM_DSC);

    const int tid = threadIdx.x;
    const int wid = tid >> 5;
    const int mrow0 = (wid & 3) * 32;
    const int ncol0 = (wid >> 2) * 64;
    const int oc = tid & 15;
    const int nb = (tid >> 4) * 8;

    #pragma unroll
    for (int p = 0; p < 2; p++) {
        int t = tid + 256 * p;
        ((float4*)Wcs)[t] = __ldg(&((const float4*)Wc_br)[t]);
    }
    if (tid < 128) {
        bias_s[tid] = __ldg(&bias[tid]);
        if (SCALE_MODE == 0) dsc[tid] = 1.f;
        else {
            int m = m0 + tid;
            float di = (m < N_NODES) ? g_dinv[m] : 1.f;
            dsc[tid] = (SCALE_MODE == 1) ? di : di * di;
        }
    }

    // stage A tile into smem
    {
        int m    = tid >> 1;
        int half = (tid & 1) * 64;
        bool ok  = (m0 + m) < N_NODES;
        const float4* src = (const float4*)&A[(size_t)(m0 + m) * 128 + half];
        float4* dst = (float4*)&S[m * LDS_T + half];
        #pragma unroll
        for (int q = 0; q < 16; q++) {
            float4 v = ok ? __ldg(&src[q]) : make_float4(0.f, 0.f, 0.f, 0.f);
            dst[q] = v;
        }
    }
    __syncthreads();

    wmma::fragment<wmma::accumulator, 16, 16, 8, float> acc[2][4];
    #pragma unroll
    for (int i = 0; i < 2; i++)
        #pragma unroll
        for (int j = 0; j < 4; j++) wmma::fill_fragment(acc[i][j], 0.f);

    #pragma unroll 4
    for (int k0 = 0; k0 < 128; k0 += 8) {
        wmma::fragment<wmma::matrix_a, 16, 16, 8, wmma::precision::tf32,
                       wmma::row_major> af[2];
        #pragma unroll
        for (int i = 0; i < 2; i++) {
            wmma::load_matrix_sync(af[i], S + (mrow0 + i * 16) * LDS_T + k0, LDS_T);
            #pragma unroll
            for (int e = 0; e < af[i].num_elements; e++)
                af[i].x[e] = wmma::__float_to_tf32(af[i].x[e]);
        }
        wmma::fragment<wmma::matrix_b, 16, 16, 8, wmma::precision::tf32,
                       wmma::row_major> bf[4];
        #pragma unroll
        for (int j = 0; j < 4; j++) {
            wmma::load_matrix_sync(bf[j], W + k0 * 128 + ncol0 + j * 16, 128);
            #pragma unroll
            for (int e = 0; e < bf[j].num_elements; e++)
                bf[j].x[e] = wmma::__float_to_tf32(bf[j].x[e]);
        }
        #pragma unroll
        for (int i = 0; i < 2; i++)
            #pragma unroll
            for (int j = 0; j < 4; j++)
                wmma::mma_sync(acc[i][j], af[i], bf[j], acc[i][j]);
    }
    __syncthreads();

    #pragma unroll
    for (int i = 0; i < 2; i++)
        #pragma unroll
        for (int j = 0; j < 4; j++)
            wmma::store_matrix_sync(S + (ncol0 + j * 16) * LDS_T + (mrow0 + i * 16),
                                    acc[i][j], LDS_T, wmma::mem_col_major);
    __syncthreads();

    // fixup: h = relu(acc * dsc[m] + bias[c]) in place
    {
        int c  = tid >> 1;
        int mh = (tid & 1) * 64;
        float bb = bias_s[c];
        #pragma unroll
        for (int q = 0; q < 16; q++) {
            int m = mh + q * 4;
            float4 v  = *(float4*)&S[c * LDS_T + m];
            float4 dv = *(const float4*)&dsc[m];
            v.x = fmaxf(fmaf(v.x, dv.x, bb), 0.f);
            v.y = fmaxf(fmaf(v.y, dv.y, bb), 0.f);
            v.z = fmaxf(fmaf(v.z, dv.z, bb), 0.f);
            v.w = fmaxf(fmaf(v.w, dv.w, bb), 0.f);
            *(float4*)&S[c * LDS_T + m] = v;
        }
    }
    __syncthreads();

    float oacc[8];
    #pragma unroll
    for (int i = 0; i < 8; i++) oacc[i] = 0.f;
    #pragma unroll 8
    for (int c = 0; c < 128; c++) {
        float w = Wcs[c * 16 + oc];
        float4 h0 = *(const float4*)&S[c * LDS_T + nb];
        float4 h1 = *(const float4*)&S[c * LDS_T + nb + 4];
        oacc[0] += h0.x * w; oacc[1] += h0.y * w;
        oacc[2] += h0.z * w; oacc[3] += h0.w * w;
        oacc[4] += h1.x * w; oacc[5] += h1.y * w;
        oacc[6] += h1.z * w; oacc[7] += h1.w * w;
    }

    if (FIRST) {
        float bcv = __ldg(&bc[oc]);
        #pragma unroll
        for (int i = 0; i < 8; i++) {
            int node = m0 + nb + i;
            if (node < N_NODES) out[node * 16 + oc] = oacc[i] + bcv;
        }
    } else {
        #pragma unroll
        for (int i = 0; i < 8; i++) {
            int node = m0 + nb + i;
            if (node < N_NODES) out[node * 16 + oc] += oacc[i];
        }
    }
}

__global__ __launch_bounds__(256, 2)
void k_mlp_ego(const float* __restrict__ x,
               const float* __restrict__ W, const float* __restrict__ b,
               const float* __restrict__ Wc, const float* __restrict__ bc,
               float* __restrict__ out) {
    extern __shared__ char smem_raw[];
    mlp_tile<0, true>(blockIdx.x * 128, x, W, b, Wc, bc, out, smem_raw);
}

__global__ __launch_bounds__(256, 2)
void k_mlp_b1(const float* __restrict__ y1f,
              const float* __restrict__ W, const float* __restrict__ b,
              const float* __restrict__ Wc, float* __restrict__ out) {
    extern __shared__ char smem_raw[];
    mlp_tile<1, false>(blockIdx.x * 128, y1f, W, b, Wc + 2048, nullptr, out, smem_raw);
}

__global__ __launch_bounds__(256, 2)
void k_mlp_b2(const float* __restrict__ y2f,
              const float* __restrict__ W, const float* __restrict__ b,
              const float* __restrict__ Wc, float* __restrict__ out) {
    extern __shared__ char smem_raw[];
    mlp_tile<2, false>(blockIdx.x * 128, y2f, W, b, Wc + 4096, nullptr, out, smem_raw);
}

// ---------------- launch: fork/join multi-stream for overlap ----------------
extern "C" void kernel_launch(void* const* d_in, const int* in_sizes, int n_in,
                              void* d_out, int out_size) {
    const float* x    = (const float*)d_in[0];
    const int*   ei   = (const int*)d_in[1];
    const float* Wego = (const float*)d_in[2];
    const float* bego = (const float*)d_in[3];
    const float* W1   = (const float*)d_in[4];
    const float* b1   = (const float*)d_in[5];
    const float* W2   = (const float*)d_in[6];
    const float* b2   = (const float*)d_in[7];
    const float* Wc   = (const float*)d_in[8];
    const float* bc   = (const float*)d_in[9];
    float*       out  = (float*)d_out;

    void *py1 = nullptr, *py2 = nullptr;
    cudaGetSymbolAddress(&py1, g_y1);
    cudaGetSymbolAddress(&py2, g_y2);

    cudaFuncSetAttribute(k_mlp_ego, cudaFuncAttributeMaxDynamicSharedMemorySize, SM_TOTAL);
    cudaFuncSetAttribute(k_mlp_b1,  cudaFuncAttributeMaxDynamicSharedMemorySize, SM_TOTAL);
    cudaFuncSetAttribute(k_mlp_b2,  cudaFuncAttributeMaxDynamicSharedMemorySize, SM_TOTAL);

    cudaStream_t sB;
    cudaStreamCreateWithFlags(&sB, cudaStreamNonBlocking);
    cudaEvent_t eFork, eS1, eS2, eJoin;
    cudaEventCreateWithFlags(&eFork, cudaEventDisableTiming);
    cudaEventCreateWithFlags(&eS1,   cudaEventDisableTiming);
    cudaEventCreateWithFlags(&eS2,   cudaEventDisableTiming);
    cudaEventCreateWithFlags(&eJoin, cudaEventDisableTiming);

    // fork: stream B handles the MLP chain (out), stream 0 the CSR+SpMM chain
    cudaEventRecord(eFork, 0);
    cudaStreamWaitEvent(sB, eFork, 0);

    // stream B: ego branch — depends only on x
    k_mlp_ego<<<MLP_CTAS, 256, SM_TOTAL, sB>>>(x, Wego, bego, Wc, bc, out);

    // stream 0: CSR build + spmm1 + spmm2
    k_zero<<<(N_NODES + 1023) / 1024, 1024>>>(ei);
    k_count<<<(N_EDGES + 255) / 256, 256>>>(ei);
    k_alloc<<<(N_NODES + 255) / 256, 256>>>();
    k_scatter<<<(N_EDGES + 255) / 256, 256>>>(ei);

    dim3 sb(32, 4);
    k_spmm<<<(N_NODES + 3) / 4, sb>>>((const float4*)x, (float4*)py1);
    cudaEventRecord(eS1, 0);
    k_spmm<<<(N_NODES + 3) / 4, sb>>>((const float4*)py1, (float4*)py2);
    cudaEventRecord(eS2, 0);

    // stream B: branch 1 after spmm1 (overlaps spmm2), branch 2 after spmm2
    cudaStreamWaitEvent(sB, eS1, 0);
    k_mlp_b1<<<MLP_CTAS, 256, SM_TOTAL, sB>>>((const float*)py1, W1, b1, Wc, out);
    cudaStreamWaitEvent(sB, eS2, 0);
    k_mlp_b2<<<MLP_CTAS, 256, SM_TOTAL, sB>>>((const float*)py2, W2, b2, Wc, out);

    // join back into stream 0
    cudaEventRecord(eJoin, sB);
    cudaStreamWaitEvent(0, eJoin, 0);

    cudaEventDestroy(eFork);
    cudaEventDestroy(eS1);
    cudaEventDestroy(eS2);
    cudaEventDestroy(eJoin);
    // stream intentionally not destroyed mid-capture-safety; tiny host-side
    // resource, created twice per process (correctness + capture call).
}